// round 5
// baseline (speedup 1.0000x reference)
#include <cuda_runtime.h>
#include <math.h>

#define TTOK 8192
#define DDIM 1024
#define HDIM 1408
#define NE   8

// ---- device scratch (static allocations only; no cudaMalloc anywhere) ----
__device__ int    g_ecount[NE];
__device__ int    g_etok[NE][TTOK];
__device__ float  g_ew[NE][TTOK];
__device__ double g_usage[NE];
__device__ float  g_hbuf[NE][TTOK][HDIM];   // ~369 MB static scratch

// ============================================================
// K0: zero output accumulator + counters
// ============================================================
__global__ void k_init(float* __restrict__ out) {
    int i = blockIdx.x * 256 + threadIdx.x;
    if (i < TTOK * DDIM) out[i] = 0.f;
    if (i < NE) { g_ecount[i] = 0; g_usage[i] = 0.0; }
}

// ============================================================
// K1: router — warp per token. logits = x_t . Wr, softmax, top-2,
// scatter into per-expert buckets, usage accumulation (double).
// ============================================================
__global__ void __launch_bounds__(128) k_router(const float* __restrict__ x,
                                                const float* __restrict__ Wr) {
    __shared__ float us[NE];
    int tid = threadIdx.x;
    if (tid < NE) us[tid] = 0.f;
    __syncthreads();

    int warp = tid >> 5, lane = tid & 31;
    int t = blockIdx.x * 4 + warp;

    float acc[NE];
#pragma unroll
    for (int e = 0; e < NE; e++) acc[e] = 0.f;

    const float* xr = x + (size_t)t * DDIM;
    for (int d = lane; d < DDIM; d += 32) {
        float xv = xr[d];
        const float* wr = Wr + d * NE;
#pragma unroll
        for (int e = 0; e < NE; e++) acc[e] += xv * wr[e];
    }
#pragma unroll
    for (int off = 16; off; off >>= 1) {
#pragma unroll
        for (int e = 0; e < NE; e++)
            acc[e] += __shfl_xor_sync(0xffffffffu, acc[e], off);
    }

    if (lane == 0) {
        float m = acc[0];
#pragma unroll
        for (int e = 1; e < NE; e++) m = fmaxf(m, acc[e]);
        float p[NE], s = 0.f;
#pragma unroll
        for (int e = 0; e < NE; e++) { p[e] = __expf(acc[e] - m); s += p[e]; }
        float inv = 1.f / s;
#pragma unroll
        for (int e = 0; e < NE; e++) p[e] *= inv;
#pragma unroll
        for (int e = 0; e < NE; e++) atomicAdd(&us[e], p[e]);

        // top-2, strict > keeps smallest index on ties (matches jax top_k)
        int i0 = 0;
#pragma unroll
        for (int e = 1; e < NE; e++) if (p[e] > p[i0]) i0 = e;
        int i1 = -1;
#pragma unroll
        for (int e = 0; e < NE; e++)
            if (e != i0 && (i1 < 0 || p[e] > p[i1])) i1 = e;

        float denom = 1.f / (p[i0] + p[i1]);
        float w0 = p[i0] * denom;
        float w1 = p[i1] * denom;

        int pos0 = atomicAdd(&g_ecount[i0], 1);
        g_etok[i0][pos0] = t; g_ew[i0][pos0] = w0;
        int pos1 = atomicAdd(&g_ecount[i1], 1);
        g_etok[i1][pos1] = t; g_ew[i1][pos1] = w1;
    }
    __syncthreads();
    if (tid < NE) atomicAdd(&g_usage[tid], (double)us[tid]);
}

// ============================================================
// K2: grouped fused gate/up/expand GEMM + activation epilogue.
// Per expert e: rows = bucketed tokens, A = gathered x rows [count x 1024],
// B = Wg/Wu/Wx [1024 x 1408]. Tile 64x64, BK=16, 4x4 per thread.
// Epilogue: hbuf = combine_w * u * (alpha*silu(g) + (1-alpha)*silu(xp))
// ============================================================
__global__ void __launch_bounds__(256) k_upgate(const float* __restrict__ x,
                                                const float* __restrict__ Wg,
                                                const float* __restrict__ Wu,
                                                const float* __restrict__ Wxp,
                                                const float* __restrict__ alpha) {
    int e = blockIdx.z;
    int count = g_ecount[e];
    int row0 = blockIdx.x * 64;
    if (row0 >= count) return;
    int n0 = blockIdx.y * 64;

    __shared__ float xs[16][65];
    __shared__ float wgs[16][64];
    __shared__ float wus[16][64];
    __shared__ float wxs[16][64];

    int tid = threadIdx.x;
    int tx = tid & 15, ty = tid >> 4;

    float ag[16], au[16], axp[16];
#pragma unroll
    for (int i = 0; i < 16; i++) { ag[i] = 0.f; au[i] = 0.f; axp[i] = 0.f; }

    // X gather-load indexing: 64 rows x 16 cols via float4
    int lr = tid >> 2;          // row in tile 0..63
    int lc = (tid & 3) * 4;     // col 0,4,8,12
    int grow = row0 + lr;
    bool rvalid = grow < count;
    int tok = rvalid ? g_etok[e][grow] : 0;
    const float* xrow = x + (size_t)tok * DDIM;

    // Weight-load indexing: 16 k-rows x 64 cols via float4
    int wr_ = tid >> 4;         // 0..15
    int wc = (tid & 15) * 4;    // 0..60
    size_t wbase = (size_t)e * DDIM * HDIM;
    const float* Wge = Wg + wbase;
    const float* Wue = Wu + wbase;
    const float* Wxe = Wxp + wbase;

    for (int k0 = 0; k0 < DDIM; k0 += 16) {
        float4 xv = rvalid ? *(const float4*)(xrow + k0 + lc)
                           : make_float4(0.f, 0.f, 0.f, 0.f);
        xs[lc + 0][lr] = xv.x;
        xs[lc + 1][lr] = xv.y;
        xs[lc + 2][lr] = xv.z;
        xs[lc + 3][lr] = xv.w;

        size_t woff = (size_t)(k0 + wr_) * HDIM + n0 + wc;
        *(float4*)&wgs[wr_][wc] = *(const float4*)(Wge + woff);
        *(float4*)&wus[wr_][wc] = *(const float4*)(Wue + woff);
        *(float4*)&wxs[wr_][wc] = *(const float4*)(Wxe + woff);
        __syncthreads();

#pragma unroll
        for (int k = 0; k < 16; k++) {
            float xm[4];
#pragma unroll
            for (int i = 0; i < 4; i++) xm[i] = xs[k][ty * 4 + i];
            float4 gv = *(float4*)&wgs[k][tx * 4];
            float4 uv = *(float4*)&wus[k][tx * 4];
            float4 pv = *(float4*)&wxs[k][tx * 4];
#pragma unroll
            for (int i = 0; i < 4; i++) {
                ag[i * 4 + 0] += xm[i] * gv.x;
                ag[i * 4 + 1] += xm[i] * gv.y;
                ag[i * 4 + 2] += xm[i] * gv.z;
                ag[i * 4 + 3] += xm[i] * gv.w;
                au[i * 4 + 0] += xm[i] * uv.x;
                au[i * 4 + 1] += xm[i] * uv.y;
                au[i * 4 + 2] += xm[i] * uv.z;
                au[i * 4 + 3] += xm[i] * uv.w;
                axp[i * 4 + 0] += xm[i] * pv.x;
                axp[i * 4 + 1] += xm[i] * pv.y;
                axp[i * 4 + 2] += xm[i] * pv.z;
                axp[i * 4 + 3] += xm[i] * pv.w;
            }
        }
        __syncthreads();
    }

    float al = alpha[e];
#pragma unroll
    for (int i = 0; i < 4; i++) {
        int grow2 = row0 + ty * 4 + i;
        if (grow2 >= count) continue;
        float w = g_ew[e][grow2];
        float* hrow = &g_hbuf[e][grow2][0];
        float4 outv;
        float vals[4];
#pragma unroll
        for (int j = 0; j < 4; j++) {
            float g  = ag[i * 4 + j];
            float u  = au[i * 4 + j];
            float xp = axp[i * 4 + j];
            float sg = g  * (1.f / (1.f + __expf(-g)));
            float sx = xp * (1.f / (1.f + __expf(-xp)));
            vals[j] = w * u * (al * sg + (1.f - al) * sx);
        }
        outv.x = vals[0]; outv.y = vals[1]; outv.z = vals[2]; outv.w = vals[3];
        *(float4*)(hrow + n0 + tx * 4) = outv;
    }
}

// ============================================================
// K3: grouped down-proj GEMM. A = hbuf[e] [count x 1408], B = Wd[e] [1408 x 1024].
// Epilogue: atomicAdd into out[token].
// ============================================================
__global__ void __launch_bounds__(256) k_down(const float* __restrict__ Wd,
                                              float* __restrict__ out) {
    int e = blockIdx.z;
    int count = g_ecount[e];
    int row0 = blockIdx.x * 64;
    if (row0 >= count) return;
    int n0 = blockIdx.y * 64;

    __shared__ float as_[16][65];
    __shared__ float ws[16][64];

    int tid = threadIdx.x;
    int tx = tid & 15, ty = tid >> 4;

    float c[16];
#pragma unroll
    for (int i = 0; i < 16; i++) c[i] = 0.f;

    int lr = tid >> 2;
    int lc = (tid & 3) * 4;
    int grow = row0 + lr;
    bool rvalid = grow < count;
    const float* arow = rvalid ? &g_hbuf[e][grow][0] : &g_hbuf[e][0][0];

    int wr_ = tid >> 4;
    int wc = (tid & 15) * 4;
    const float* Wde = Wd + (size_t)e * HDIM * DDIM;

    for (int k0 = 0; k0 < HDIM; k0 += 16) {
        float4 av = rvalid ? *(const float4*)(arow + k0 + lc)
                           : make_float4(0.f, 0.f, 0.f, 0.f);
        as_[lc + 0][lr] = av.x;
        as_[lc + 1][lr] = av.y;
        as_[lc + 2][lr] = av.z;
        as_[lc + 3][lr] = av.w;

        *(float4*)&ws[wr_][wc] =
            *(const float4*)(Wde + (size_t)(k0 + wr_) * DDIM + n0 + wc);
        __syncthreads();

#pragma unroll
        for (int k = 0; k < 16; k++) {
            float am[4];
#pragma unroll
            for (int i = 0; i < 4; i++) am[i] = as_[k][ty * 4 + i];
            float4 wv = *(float4*)&ws[k][tx * 4];
#pragma unroll
            for (int i = 0; i < 4; i++) {
                c[i * 4 + 0] += am[i] * wv.x;
                c[i * 4 + 1] += am[i] * wv.y;
                c[i * 4 + 2] += am[i] * wv.z;
                c[i * 4 + 3] += am[i] * wv.w;
            }
        }
        __syncthreads();
    }

#pragma unroll
    for (int i = 0; i < 4; i++) {
        int grow2 = row0 + ty * 4 + i;
        if (grow2 >= count) continue;
        int tok = g_etok[e][grow2];
        float* orow = out + (size_t)tok * DDIM + n0 + tx * 4;
#pragma unroll
        for (int j = 0; j < 4; j++) atomicAdd(&orow[j], c[i * 4 + j]);
    }
}

// ============================================================
// K4: load-balancing loss scalar
// ============================================================
__global__ void k_final(float* __restrict__ out, int out_size) {
    if (threadIdx.x == 0 && blockIdx.x == 0) {
        double s = 0.0;
        for (int e = 0; e < NE; e++) {
            double u = g_usage[e] / (double)TTOK - 1.0 / (double)NE;
            s += u * u;
        }
        float lb = (float)(0.01 * s / (double)NE);
        if (out_size > TTOK * DDIM) out[TTOK * DDIM] = lb;
    }
}

// ============================================================
extern "C" void kernel_launch(void* const* d_in, const int* in_sizes, int n_in,
                              void* d_out, int out_size) {
    const float* x     = (const float*)d_in[0];
    const float* Wr    = (const float*)d_in[1];
    const float* Wg    = (const float*)d_in[2];
    const float* Wu    = (const float*)d_in[3];
    const float* Wxp   = (const float*)d_in[4];
    const float* Wd    = (const float*)d_in[5];
    const float* alpha = (const float*)d_in[6];
    float* out = (float*)d_out;

    // K0: zero out + counters
    k_init<<<(TTOK * DDIM + 255) / 256, 256>>>(out);

    // K1: router + dispatch
    k_router<<<TTOK / 4, 128>>>(x, Wr);

    // K2: fused gate/up/expand grouped GEMM + activation
    dim3 g2(TTOK / 64, HDIM / 64, NE);
    k_upgate<<<g2, 256>>>(x, Wg, Wu, Wxp, alpha);

    // K3: down-proj grouped GEMM + scatter-accumulate
    dim3 g3(TTOK / 64, DDIM / 64, NE);
    k_down<<<g3, 256>>>(Wd, out);

    // K4: lb loss
    k_final<<<1, 32>>>(out, out_size);
}

// round 14
// speedup vs baseline: 2.0989x; 2.0989x over previous
#include <cuda_runtime.h>
#include <cuda_bf16.h>
#include <cstdint>
#include <math.h>

#define TTOK 8192
#define DDIM 1024
#define HDIM 1408
#define NE   8

// ---- static device scratch ----
__device__ int    g_ecount[NE];
__device__ int    g_etok[NE][TTOK];
__device__ float  g_ew[NE][TTOK];
__device__ double g_usage[NE];
__device__ __align__(256) float g_hbuf[(size_t)NE * TTOK * HDIM];            // 369 MB
__device__ __align__(256) __nv_bfloat16 g_wg[(size_t)NE * 2 * HDIM * DDIM];  // [E][2][H][D] hi/lo
__device__ __align__(256) __nv_bfloat16 g_wu[(size_t)NE * 2 * HDIM * DDIM];
__device__ __align__(256) __nv_bfloat16 g_wx[(size_t)NE * 2 * HDIM * DDIM];
__device__ __align__(256) __nv_bfloat16 g_wd[(size_t)NE * 2 * DDIM * HDIM];  // [E][2][D][H]

// device-side symbol resolution (NEVER pass __device__ symbols from host!)
__device__ __forceinline__ __nv_bfloat16* wsel_dst(int which) {
    switch (which) {
        case 0:  return g_wg;
        case 1:  return g_wu;
        case 2:  return g_wx;
        default: return g_wd;
    }
}

// ---- helpers ----
__device__ __forceinline__ void mma_acc(float* d, const uint32_t* a, uint32_t b0, uint32_t b1) {
    asm volatile("mma.sync.aligned.m16n8k16.row.col.f32.bf16.bf16.f32 "
        "{%0,%1,%2,%3}, {%4,%5,%6,%7}, {%8,%9}, {%0,%1,%2,%3};"
        : "+f"(d[0]), "+f"(d[1]), "+f"(d[2]), "+f"(d[3])
        : "r"(a[0]), "r"(a[1]), "r"(a[2]), "r"(a[3]), "r"(b0), "r"(b1));
}
__device__ __forceinline__ uint32_t pack_hi(float a, float b, uint32_t& lo) {
    __nv_bfloat16 ha = __float2bfloat16(a), hb = __float2bfloat16(b);
    __nv_bfloat16 la = __float2bfloat16(a - __bfloat162float(ha));
    __nv_bfloat16 lb = __float2bfloat16(b - __bfloat162float(hb));
    lo = ((uint32_t)__bfloat16_as_ushort(lb) << 16) | __bfloat16_as_ushort(la);
    return ((uint32_t)__bfloat16_as_ushort(hb) << 16) | __bfloat16_as_ushort(ha);
}

// smem index helpers (unsigned short element offsets, row stride 36)
#define SA(p, r, k)    ((((p) * 128) + (r)) * 36 + (k))
#define SB(j, p, r, k) ((((((j) * 2) + (p)) * 64) + (r)) * 36 + (k))

// ================= K0: zero out + counters =================
__global__ void k_init(float* __restrict__ out) {
    int i = blockIdx.x * 256 + threadIdx.x;
    if (i < TTOK * DDIM) out[i] = 0.f;
    if (i < NE) { g_ecount[i] = 0; g_usage[i] = 0.0; }
}

// ===== K1: transpose + hi/lo split: src [E][K][N] f32 -> g_w*[E][2][N][K] bf16 =====
__global__ void k_tsplit(const float* __restrict__ src, int which, int K, int N) {
    __shared__ float t[32][33];
    __nv_bfloat16* dst = wsel_dst(which);   // resolved in DEVICE code
    int e = blockIdx.z;
    int n0 = blockIdx.x * 32, k0 = blockIdx.y * 32;
    int tx = threadIdx.x, ty = threadIdx.y;   // 32 x 8
    const float* s = src + (size_t)e * K * N;
#pragma unroll
    for (int i = 0; i < 32; i += 8)
        t[ty + i][tx] = s[(size_t)(k0 + ty + i) * N + n0 + tx];
    __syncthreads();
    size_t pl = (size_t)K * N;
    size_t b0 = (size_t)e * 2 * pl;
#pragma unroll
    for (int i = 0; i < 32; i += 8) {
        float v = t[tx][ty + i];
        __nv_bfloat16 hi = __float2bfloat16(v);
        __nv_bfloat16 lo = __float2bfloat16(v - __bfloat162float(hi));
        size_t o = b0 + (size_t)(n0 + ty + i) * K + (k0 + tx);
        dst[o] = hi; dst[o + pl] = lo;
    }
}

// ===== K2: router (R1-proven) =====
__global__ void __launch_bounds__(128) k_router(const float* __restrict__ x,
                                                const float* __restrict__ Wr) {
    __shared__ float us[NE];
    int tid = threadIdx.x;
    if (tid < NE) us[tid] = 0.f;
    __syncthreads();
    int warp = tid >> 5, lane = tid & 31;
    int t = blockIdx.x * 4 + warp;
    float acc[NE];
#pragma unroll
    for (int e = 0; e < NE; e++) acc[e] = 0.f;
    const float* xr = x + (size_t)t * DDIM;
    for (int d = lane; d < DDIM; d += 32) {
        float xv = xr[d];
        const float* wr = Wr + d * NE;
#pragma unroll
        for (int e = 0; e < NE; e++) acc[e] += xv * wr[e];
    }
#pragma unroll
    for (int off = 16; off; off >>= 1)
#pragma unroll
        for (int e = 0; e < NE; e++)
            acc[e] += __shfl_xor_sync(0xffffffffu, acc[e], off);
    if (lane == 0) {
        float m = acc[0];
#pragma unroll
        for (int e = 1; e < NE; e++) m = fmaxf(m, acc[e]);
        float p[NE], s = 0.f;
#pragma unroll
        for (int e = 0; e < NE; e++) { p[e] = __expf(acc[e] - m); s += p[e]; }
        float inv = 1.f / s;
#pragma unroll
        for (int e = 0; e < NE; e++) p[e] *= inv;
#pragma unroll
        for (int e = 0; e < NE; e++) atomicAdd(&us[e], p[e]);
        int i0 = 0;
#pragma unroll
        for (int e = 1; e < NE; e++) if (p[e] > p[i0]) i0 = e;
        int i1 = -1;
#pragma unroll
        for (int e = 0; e < NE; e++)
            if (e != i0 && (i1 < 0 || p[e] > p[i1])) i1 = e;
        float den = 1.f / (p[i0] + p[i1]);
        int pos0 = atomicAdd(&g_ecount[i0], 1);
        g_etok[i0][pos0] = t; g_ew[i0][pos0] = p[i0] * den;
        int pos1 = atomicAdd(&g_ecount[i1], 1);
        g_etok[i1][pos1] = t; g_ew[i1][pos1] = p[i1] * den;
    }
    __syncthreads();
    if (tid < NE) atomicAdd(&g_usage[tid], (double)us[tid]);
}

// ===== K3 body: fused up/gate/expand HMMA GEMM (static smem, reg-prefetch) =====
template<bool HG, bool HX>
__device__ __forceinline__ void upgate_body(unsigned short* sA, unsigned short* sB,
                                            const float* __restrict__ xg,
                                            int e, int count, int row0, int n0, float al) {
    constexpr int NM = 1 + (HG ? 1 : 0) + (HX ? 1 : 0);
    const __nv_bfloat16* wsl[3];
    wsl[0] = g_wu;
    wsl[1] = HG ? g_wg : g_wx;
    wsl[2] = g_wx;

    int tid = threadIdx.x, lane = tid & 31, w = tid >> 5;
    int wM = w & 3, wN = w >> 2;
    int g = lane >> 2, tig = lane & 3;

    int ar = tid >> 1, ahalf = (tid & 1) * 16;
    int tok = g_etok[e][row0 + ar];
    const float* asrc = xg + (size_t)tok * DDIM + ahalf;
    int br = tid >> 2, bk = (tid & 3) * 8;

    float4 aR[4];
    uint4  bR[3][2];

    float acc[NM][2][4][4];
#pragma unroll
    for (int j = 0; j < NM; j++)
#pragma unroll
        for (int mf = 0; mf < 2; mf++)
#pragma unroll
            for (int nf = 0; nf < 4; nf++)
#pragma unroll
                for (int q = 0; q < 4; q++) acc[j][mf][nf][q] = 0.f;

    // initial loads (chunk 0)
#pragma unroll
    for (int q = 0; q < 4; q++) aR[q] = *(const float4*)(asrc + q * 4);
#pragma unroll
    for (int j = 0; j < NM; j++)
#pragma unroll
        for (int p = 0; p < 2; p++)
            bR[j][p] = *(const uint4*)(wsl[j] + ((size_t)(e * 2 + p) * HDIM + n0 + br) * DDIM + bk);

    const int NK = DDIM / 32;
    for (int c = 0; c < NK; c++) {
        // store prefetched regs to smem
#pragma unroll
        for (int q = 0; q < 4; q++) {
            uint32_t l0, l1;
            uint32_t h0 = pack_hi(aR[q].x, aR[q].y, l0);
            uint32_t h1 = pack_hi(aR[q].z, aR[q].w, l1);
            int k = ahalf + q * 4;
            *(uint32_t*)&sA[SA(0, ar, k)]     = h0;
            *(uint32_t*)&sA[SA(0, ar, k + 2)] = h1;
            *(uint32_t*)&sA[SA(1, ar, k)]     = l0;
            *(uint32_t*)&sA[SA(1, ar, k + 2)] = l1;
        }
#pragma unroll
        for (int j = 0; j < NM; j++)
#pragma unroll
            for (int p = 0; p < 2; p++) {
                *(uint32_t*)&sB[SB(j, p, br, bk)]     = bR[j][p].x;
                *(uint32_t*)&sB[SB(j, p, br, bk + 2)] = bR[j][p].y;
                *(uint32_t*)&sB[SB(j, p, br, bk + 4)] = bR[j][p].z;
                *(uint32_t*)&sB[SB(j, p, br, bk + 6)] = bR[j][p].w;
            }
        __syncthreads();

        // issue next chunk's global loads (overlap with compute below)
        if (c + 1 < NK) {
            int k0 = (c + 1) * 32;
#pragma unroll
            for (int q = 0; q < 4; q++) aR[q] = *(const float4*)(asrc + k0 + q * 4);
#pragma unroll
            for (int j = 0; j < NM; j++)
#pragma unroll
                for (int p = 0; p < 2; p++)
                    bR[j][p] = *(const uint4*)(wsl[j] + ((size_t)(e * 2 + p) * HDIM + n0 + br) * DDIM + k0 + bk);
        }

        // compute chunk c
#pragma unroll
        for (int kk = 0; kk < 2; kk++) {
            int kc = kk * 16 + tig * 2;
            uint32_t ah[2][4], alo_[2][4];
#pragma unroll
            for (int mf = 0; mf < 2; mf++) {
                int rb = wM * 32 + mf * 16;
                ah[mf][0]   = *(const uint32_t*)&sA[SA(0, rb + g,     kc)];
                ah[mf][1]   = *(const uint32_t*)&sA[SA(0, rb + g + 8, kc)];
                ah[mf][2]   = *(const uint32_t*)&sA[SA(0, rb + g,     kc + 8)];
                ah[mf][3]   = *(const uint32_t*)&sA[SA(0, rb + g + 8, kc + 8)];
                alo_[mf][0] = *(const uint32_t*)&sA[SA(1, rb + g,     kc)];
                alo_[mf][1] = *(const uint32_t*)&sA[SA(1, rb + g + 8, kc)];
                alo_[mf][2] = *(const uint32_t*)&sA[SA(1, rb + g,     kc + 8)];
                alo_[mf][3] = *(const uint32_t*)&sA[SA(1, rb + g + 8, kc + 8)];
            }
#pragma unroll
            for (int j = 0; j < NM; j++)
#pragma unroll
                for (int nf = 0; nf < 4; nf++) {
                    int brw = wN * 32 + nf * 8 + g;
                    uint32_t bh0 = *(const uint32_t*)&sB[SB(j, 0, brw, kc)];
                    uint32_t bh1 = *(const uint32_t*)&sB[SB(j, 0, brw, kc + 8)];
                    uint32_t bl0 = *(const uint32_t*)&sB[SB(j, 1, brw, kc)];
                    uint32_t bl1 = *(const uint32_t*)&sB[SB(j, 1, brw, kc + 8)];
#pragma unroll
                    for (int mf = 0; mf < 2; mf++) {
                        mma_acc(acc[j][mf][nf], ah[mf],   bh0, bh1);
                        mma_acc(acc[j][mf][nf], ah[mf],   bl0, bl1);
                        mma_acc(acc[j][mf][nf], alo_[mf], bh0, bh1);
                    }
                }
        }
        __syncthreads();
    }

    // epilogue -> f32 g_hbuf
#pragma unroll
    for (int mf = 0; mf < 2; mf++)
#pragma unroll
        for (int nf = 0; nf < 4; nf++) {
            int col = n0 + wN * 32 + nf * 8 + tig * 2;
#pragma unroll
            for (int hh = 0; hh < 2; hh++) {
                int rl = row0 + wM * 32 + mf * 16 + g + hh * 8;
                if (rl < count) {
                    float wc = g_ew[e][rl];
                    float2 st;
                    float v[2];
#pragma unroll
                    for (int q = 0; q < 2; q++) {
                        int i = hh * 2 + q;
                        float t = 0.f;
                        if (HG) {
                            float gv = acc[1][mf][nf][i];
                            t += al * (gv * (1.f / (1.f + __expf(-gv))));
                        }
                        if (HX) {
                            float xv = acc[HG ? 2 : 1][mf][nf][i];
                            t += (1.f - al) * (xv * (1.f / (1.f + __expf(-xv))));
                        }
                        v[q] = wc * acc[0][mf][nf][i] * t;
                    }
                    st.x = v[0]; st.y = v[1];
                    *(float2*)&g_hbuf[(size_t)(e * TTOK + rl) * HDIM + col] = st;
                }
            }
        }
}

__global__ void __launch_bounds__(256) k_upgate(const float* __restrict__ x,
                                                const float* __restrict__ alpha) {
    __shared__ unsigned short sA[2 * 128 * 36];       // 18432 B
    __shared__ unsigned short sB[3 * 2 * 64 * 36];    // 27648 B
    int e = blockIdx.z;
    int count = g_ecount[e];
    int row0 = blockIdx.x * 128;
    if (row0 >= count) return;
    int n0 = blockIdx.y * 64;
    float al = alpha[e];
    bool hg = (al != 0.f), hx = (al != 1.f);
    if (hg && hx)      upgate_body<true,  true >(sA, sB, x, e, count, row0, n0, al);
    else if (hg)       upgate_body<true,  false>(sA, sB, x, e, count, row0, n0, al);
    else               upgate_body<false, true >(sA, sB, x, e, count, row0, n0, al);
}

// ===== K4: down-proj HMMA GEMM + atomicAdd scatter =====
__global__ void __launch_bounds__(256) k_down(float* __restrict__ out) {
    __shared__ unsigned short sA[2 * 128 * 36];       // 18432 B
    __shared__ unsigned short sB[1 * 2 * 64 * 36];    // 9216 B
    int e = blockIdx.z;
    int count = g_ecount[e];
    int row0 = blockIdx.x * 128;
    if (row0 >= count) return;
    int n0 = blockIdx.y * 64;

    int tid = threadIdx.x, lane = tid & 31, w = tid >> 5;
    int wM = w & 3, wN = w >> 2;
    int g = lane >> 2, tig = lane & 3;

    int ar = tid >> 1, ahalf = (tid & 1) * 16;
    const float* asrc = g_hbuf + (size_t)(e * TTOK + row0 + ar) * HDIM + ahalf;
    int br = tid >> 2, bk = (tid & 3) * 8;

    float4 aR[4];
    uint4  bR[2];

    float acc[2][4][4];
#pragma unroll
    for (int mf = 0; mf < 2; mf++)
#pragma unroll
        for (int nf = 0; nf < 4; nf++)
#pragma unroll
            for (int q = 0; q < 4; q++) acc[mf][nf][q] = 0.f;

#pragma unroll
    for (int q = 0; q < 4; q++) aR[q] = *(const float4*)(asrc + q * 4);
#pragma unroll
    for (int p = 0; p < 2; p++)
        bR[p] = *(const uint4*)(g_wd + ((size_t)(e * 2 + p) * DDIM + n0 + br) * HDIM + bk);

    const int NK = HDIM / 32;   // 44
    for (int c = 0; c < NK; c++) {
#pragma unroll
        for (int q = 0; q < 4; q++) {
            uint32_t l0, l1;
            uint32_t h0 = pack_hi(aR[q].x, aR[q].y, l0);
            uint32_t h1 = pack_hi(aR[q].z, aR[q].w, l1);
            int k = ahalf + q * 4;
            *(uint32_t*)&sA[SA(0, ar, k)]     = h0;
            *(uint32_t*)&sA[SA(0, ar, k + 2)] = h1;
            *(uint32_t*)&sA[SA(1, ar, k)]     = l0;
            *(uint32_t*)&sA[SA(1, ar, k + 2)] = l1;
        }
#pragma unroll
        for (int p = 0; p < 2; p++) {
            *(uint32_t*)&sB[SB(0, p, br, bk)]     = bR[p].x;
            *(uint32_t*)&sB[SB(0, p, br, bk + 2)] = bR[p].y;
            *(uint32_t*)&sB[SB(0, p, br, bk + 4)] = bR[p].z;
            *(uint32_t*)&sB[SB(0, p, br, bk + 6)] = bR[p].w;
        }
        __syncthreads();

        if (c + 1 < NK) {
            int k0 = (c + 1) * 32;
#pragma unroll
            for (int q = 0; q < 4; q++) aR[q] = *(const float4*)(asrc + k0 + q * 4);
#pragma unroll
            for (int p = 0; p < 2; p++)
                bR[p] = *(const uint4*)(g_wd + ((size_t)(e * 2 + p) * DDIM + n0 + br) * HDIM + k0 + bk);
        }

#pragma unroll
        for (int kk = 0; kk < 2; kk++) {
            int kc = kk * 16 + tig * 2;
            uint32_t ah[2][4], alo_[2][4];
#pragma unroll
            for (int mf = 0; mf < 2; mf++) {
                int rb = wM * 32 + mf * 16;
                ah[mf][0]   = *(const uint32_t*)&sA[SA(0, rb + g,     kc)];
                ah[mf][1]   = *(const uint32_t*)&sA[SA(0, rb + g + 8, kc)];
                ah[mf][2]   = *(const uint32_t*)&sA[SA(0, rb + g,     kc + 8)];
                ah[mf][3]   = *(const uint32_t*)&sA[SA(0, rb + g + 8, kc + 8)];
                alo_[mf][0] = *(const uint32_t*)&sA[SA(1, rb + g,     kc)];
                alo_[mf][1] = *(const uint32_t*)&sA[SA(1, rb + g + 8, kc)];
                alo_[mf][2] = *(const uint32_t*)&sA[SA(1, rb + g,     kc + 8)];
                alo_[mf][3] = *(const uint32_t*)&sA[SA(1, rb + g + 8, kc + 8)];
            }
#pragma unroll
            for (int nf = 0; nf < 4; nf++) {
                int brw = wN * 32 + nf * 8 + g;
                uint32_t bh0 = *(const uint32_t*)&sB[SB(0, 0, brw, kc)];
                uint32_t bh1 = *(const uint32_t*)&sB[SB(0, 0, brw, kc + 8)];
                uint32_t bl0 = *(const uint32_t*)&sB[SB(0, 1, brw, kc)];
                uint32_t bl1 = *(const uint32_t*)&sB[SB(0, 1, brw, kc + 8)];
#pragma unroll
                for (int mf = 0; mf < 2; mf++) {
                    mma_acc(acc[mf][nf], ah[mf],   bh0, bh1);
                    mma_acc(acc[mf][nf], ah[mf],   bl0, bl1);
                    mma_acc(acc[mf][nf], alo_[mf], bh0, bh1);
                }
            }
        }
        __syncthreads();
    }

    // epilogue: atomicAdd scatter into out
#pragma unroll
    for (int mf = 0; mf < 2; mf++)
#pragma unroll
        for (int nf = 0; nf < 4; nf++) {
            int col = n0 + wN * 32 + nf * 8 + tig * 2;
#pragma unroll
            for (int hh = 0; hh < 2; hh++) {
                int rl = row0 + wM * 32 + mf * 16 + g + hh * 8;
                if (rl < count) {
                    int tok = g_etok[e][rl];
                    float* orow = out + (size_t)tok * DDIM + col;
                    atomicAdd(&orow[0], acc[mf][nf][hh * 2 + 0]);
                    atomicAdd(&orow[1], acc[mf][nf][hh * 2 + 1]);
                }
            }
        }
}

// ===== K5: LB loss =====
__global__ void k_final(float* __restrict__ out, int out_size) {
    if (threadIdx.x == 0 && blockIdx.x == 0) {
        double s = 0.0;
        for (int e = 0; e < NE; e++) {
            double u = g_usage[e] / (double)TTOK - 1.0 / (double)NE;
            s += u * u;
        }
        float lb = (float)(0.01 * s / (double)NE);
        if (out_size > TTOK * DDIM) out[TTOK * DDIM] = lb;
    }
}

// ============================================================
extern "C" void kernel_launch(void* const* d_in, const int* in_sizes, int n_in,
                              void* d_out, int out_size) {
    const float* x     = (const float*)d_in[0];
    const float* Wr    = (const float*)d_in[1];
    const float* Wg    = (const float*)d_in[2];
    const float* Wu    = (const float*)d_in[3];
    const float* Wxp   = (const float*)d_in[4];
    const float* Wd    = (const float*)d_in[5];
    const float* alpha = (const float*)d_in[6];
    float* out = (float*)d_out;

    // K0: zero out + counters
    k_init<<<(TTOK * DDIM + 255) / 256, 256>>>(out);

    // weight transpose + hi/lo split (dst selected in device code)
    dim3 tb(32, 8);
    dim3 tg_h(HDIM / 32, DDIM / 32, NE);   // K=DDIM, N=HDIM
    k_tsplit<<<tg_h, tb>>>(Wg,  0, DDIM, HDIM);
    k_tsplit<<<tg_h, tb>>>(Wu,  1, DDIM, HDIM);
    k_tsplit<<<tg_h, tb>>>(Wxp, 2, DDIM, HDIM);
    dim3 tg_d(DDIM / 32, HDIM / 32, NE);   // K=HDIM, N=DDIM
    k_tsplit<<<tg_d, tb>>>(Wd,  3, HDIM, DDIM);

    // router
    k_router<<<TTOK / 4, 128>>>(x, Wr);

    // fused up/gate/expand HMMA GEMM
    dim3 g2(TTOK / 128, HDIM / 64, NE);    // 64 x 22 x 8
    k_upgate<<<g2, 256>>>(x, alpha);

    // down-proj HMMA GEMM + scatter
    dim3 g3(TTOK / 128, DDIM / 64, NE);    // 64 x 16 x 8
    k_down<<<g3, 256>>>(out);

    // LB loss
    k_final<<<1, 32>>>(out, out_size);
}

// round 16
// speedup vs baseline: 2.7641x; 1.3170x over previous
#include <cuda_runtime.h>
#include <cuda_bf16.h>
#include <cstdint>
#include <math.h>

#define TTOK 8192
#define DDIM 1024
#define HDIM 1408
#define NE   8

// ---- static device scratch ----
__device__ int    g_ecount[NE];
__device__ int    g_etok[NE][TTOK];
__device__ float  g_ew[NE][TTOK];
__device__ double g_usage[NE];
__device__ __align__(256) __nv_bfloat16 g_xh[(size_t)TTOK * DDIM];           // x hi plane
__device__ __align__(256) __nv_bfloat16 g_xl[(size_t)TTOK * DDIM];           // x lo plane
__device__ __align__(256) __nv_bfloat16 g_hh[(size_t)NE * TTOK * HDIM];      // h hi plane
__device__ __align__(256) __nv_bfloat16 g_hl[(size_t)NE * TTOK * HDIM];      // h lo plane
__device__ __align__(256) __nv_bfloat16 g_wg[(size_t)NE * 2 * HDIM * DDIM];  // [E][2][H][D]
__device__ __align__(256) __nv_bfloat16 g_wu[(size_t)NE * 2 * HDIM * DDIM];
__device__ __align__(256) __nv_bfloat16 g_wx[(size_t)NE * 2 * HDIM * DDIM];
__device__ __align__(256) __nv_bfloat16 g_wd[(size_t)NE * 2 * DDIM * HDIM];  // [E][2][D][H]

// device-side symbol resolution (NEVER pass __device__ symbols from host!)
__device__ __forceinline__ __nv_bfloat16* wsel_dst(int which) {
    switch (which) {
        case 0:  return g_wg;
        case 1:  return g_wu;
        case 2:  return g_wx;
        default: return g_wd;
    }
}

// ---- helpers ----
__device__ __forceinline__ uint32_t smem_u32(const void* p) {
    uint32_t a;
    asm("{ .reg .u64 t; cvta.to.shared.u64 t, %1; cvt.u32.u64 %0, t; }" : "=r"(a) : "l"(p));
    return a;
}
__device__ __forceinline__ void mma_acc(float* d, const uint32_t* a, uint32_t b0, uint32_t b1) {
    asm volatile("mma.sync.aligned.m16n8k16.row.col.f32.bf16.bf16.f32 "
        "{%0,%1,%2,%3}, {%4,%5,%6,%7}, {%8,%9}, {%0,%1,%2,%3};"
        : "+f"(d[0]), "+f"(d[1]), "+f"(d[2]), "+f"(d[3])
        : "r"(a[0]), "r"(a[1]), "r"(a[2]), "r"(a[3]), "r"(b0), "r"(b1));
}
#define LDSM4(r0, r1, r2, r3, a) \
    asm volatile("ldmatrix.sync.aligned.m8n8.x4.shared.b16 {%0,%1,%2,%3}, [%4];" \
        : "=r"(r0), "=r"(r1), "=r"(r2), "=r"(r3) : "r"(a))

__device__ __forceinline__ uint32_t pack_hi(float a, float b, uint32_t& lo) {
    __nv_bfloat16 ha = __float2bfloat16(a), hb = __float2bfloat16(b);
    __nv_bfloat16 la = __float2bfloat16(a - __bfloat162float(ha));
    __nv_bfloat16 lb = __float2bfloat16(b - __bfloat162float(hb));
    lo = ((uint32_t)__bfloat16_as_ushort(lb) << 16) | __bfloat16_as_ushort(la);
    return ((uint32_t)__bfloat16_as_ushort(hb) << 16) | __bfloat16_as_ushort(ha);
}

// ================= K0: zero out + counters =================
__global__ void k_init(float* __restrict__ out) {
    int i = blockIdx.x * 256 + threadIdx.x;
    if (i < TTOK * DDIM) out[i] = 0.f;
    if (i < NE) { g_ecount[i] = 0; g_usage[i] = 0.0; }
}

// ===== K1: x -> bf16 hi/lo planes =====
__global__ void k_splitx(const float* __restrict__ x) {
    size_t i = ((size_t)blockIdx.x * 256 + threadIdx.x) * 4;
    if (i >= (size_t)TTOK * DDIM) return;
    float4 v = *(const float4*)(x + i);
    uint32_t l0, l1;
    uint32_t h0 = pack_hi(v.x, v.y, l0);
    uint32_t h1 = pack_hi(v.z, v.w, l1);
    *(uint32_t*)&g_xh[i]     = h0;
    *(uint32_t*)&g_xh[i + 2] = h1;
    *(uint32_t*)&g_xl[i]     = l0;
    *(uint32_t*)&g_xl[i + 2] = l1;
}

// ===== K2: transpose + hi/lo split: src [E][K][N] f32 -> g_w*[E][2][N][K] bf16 =====
__global__ void k_tsplit(const float* __restrict__ src, int which, int K, int N) {
    __shared__ float t[32][33];
    __nv_bfloat16* dst = wsel_dst(which);
    int e = blockIdx.z;
    int n0 = blockIdx.x * 32, k0 = blockIdx.y * 32;
    int tx = threadIdx.x, ty = threadIdx.y;   // 32 x 8
    const float* s = src + (size_t)e * K * N;
#pragma unroll
    for (int i = 0; i < 32; i += 8)
        t[ty + i][tx] = s[(size_t)(k0 + ty + i) * N + n0 + tx];
    __syncthreads();
    size_t pl = (size_t)K * N;
    size_t b0 = (size_t)e * 2 * pl;
#pragma unroll
    for (int i = 0; i < 32; i += 8) {
        float v = t[tx][ty + i];
        __nv_bfloat16 hi = __float2bfloat16(v);
        __nv_bfloat16 lo = __float2bfloat16(v - __bfloat162float(hi));
        size_t o = b0 + (size_t)(n0 + ty + i) * K + (k0 + tx);
        dst[o] = hi; dst[o + pl] = lo;
    }
}

// ===== K3: router (proven) =====
__global__ void __launch_bounds__(128) k_router(const float* __restrict__ x,
                                                const float* __restrict__ Wr) {
    __shared__ float us[NE];
    int tid = threadIdx.x;
    if (tid < NE) us[tid] = 0.f;
    __syncthreads();
    int warp = tid >> 5, lane = tid & 31;
    int t = blockIdx.x * 4 + warp;
    float acc[NE];
#pragma unroll
    for (int e = 0; e < NE; e++) acc[e] = 0.f;
    const float* xr = x + (size_t)t * DDIM;
    for (int d = lane; d < DDIM; d += 32) {
        float xv = xr[d];
        const float* wr = Wr + d * NE;
#pragma unroll
        for (int e = 0; e < NE; e++) acc[e] += xv * wr[e];
    }
#pragma unroll
    for (int off = 16; off; off >>= 1)
#pragma unroll
        for (int e = 0; e < NE; e++)
            acc[e] += __shfl_xor_sync(0xffffffffu, acc[e], off);
    if (lane == 0) {
        float m = acc[0];
#pragma unroll
        for (int e = 1; e < NE; e++) m = fmaxf(m, acc[e]);
        float p[NE], s = 0.f;
#pragma unroll
        for (int e = 0; e < NE; e++) { p[e] = __expf(acc[e] - m); s += p[e]; }
        float inv = 1.f / s;
#pragma unroll
        for (int e = 0; e < NE; e++) p[e] *= inv;
#pragma unroll
        for (int e = 0; e < NE; e++) atomicAdd(&us[e], p[e]);
        int i0 = 0;
#pragma unroll
        for (int e = 1; e < NE; e++) if (p[e] > p[i0]) i0 = e;
        int i1 = -1;
#pragma unroll
        for (int e = 0; e < NE; e++)
            if (e != i0 && (i1 < 0 || p[e] > p[i1])) i1 = e;
        float den = 1.f / (p[i0] + p[i1]);
        int pos0 = atomicAdd(&g_ecount[i0], 1);
        g_etok[i0][pos0] = t; g_ew[i0][pos0] = p[i0] * den;
        int pos1 = atomicAdd(&g_ecount[i1], 1);
        g_etok[i1][pos1] = t; g_ew[i1][pos1] = p[i1] * den;
    }
    __syncthreads();
    if (tid < NE) atomicAdd(&g_usage[tid], (double)us[tid]);
}

// ============================================================
// Fast upgate body: NM=2 (up + one of gate/expand), ldmatrix + planes.
// smem: sA [2][128][40], sB [2 mats][2 planes][64][40]  (stride 40 shorts = 80B)
// ============================================================
__device__ void upgate_fast(unsigned short* sbuf, int e, int count, int row0, int n0,
                            const __nv_bfloat16* __restrict__ w2, float coef) {
    const int ST = 40;
    unsigned short* sA = sbuf;            // 10240 shorts
    unsigned short* sB = sbuf + 10240;    // 10240 shorts
    int tid = threadIdx.x, lane = tid & 31, w = tid >> 5;
    int wM = w & 3, wN = w >> 2;
    int g = lane >> 2, tig = lane & 3;
    int i8 = lane & 7, seg = lane >> 3;

    int ar = tid >> 1, kh = (tid & 1) * 16;
    int tok = g_etok[e][row0 + ar];
    const __nv_bfloat16* axh = g_xh + (size_t)tok * DDIM + kh;
    const __nv_bfloat16* axl = g_xl + (size_t)tok * DDIM + kh;
    int br = tid >> 2, bk = (tid & 3) * 8;
    const __nv_bfloat16* bsrc[2][2];
    bsrc[0][0] = g_wu + ((size_t)(e * 2 + 0) * HDIM + n0 + br) * DDIM + bk;
    bsrc[0][1] = g_wu + ((size_t)(e * 2 + 1) * HDIM + n0 + br) * DDIM + bk;
    bsrc[1][0] = w2   + ((size_t)(e * 2 + 0) * HDIM + n0 + br) * DDIM + bk;
    bsrc[1][1] = w2   + ((size_t)(e * 2 + 1) * HDIM + n0 + br) * DDIM + bk;

    uint32_t sAu = smem_u32(sA), sBu = smem_u32(sB);
    int arow_l = (seg & 1) * 8 + i8;
    int acol_l = (seg >> 1) * 8;
    int brow_l = (seg >> 1) * 8 + i8;
    int bcol_l = (seg & 1) * 8;

    float acc[2][2][4][4];
#pragma unroll
    for (int j = 0; j < 2; j++)
#pragma unroll
        for (int mf = 0; mf < 2; mf++)
#pragma unroll
            for (int nf = 0; nf < 4; nf++)
#pragma unroll
                for (int q = 0; q < 4; q++) acc[j][mf][nf][q] = 0.f;

    uint4 aPf[2][2], bPf[2][2];
#pragma unroll
    for (int p = 0; p < 2; p++) {
        const __nv_bfloat16* s = p ? axl : axh;
        aPf[p][0] = *(const uint4*)(s);
        aPf[p][1] = *(const uint4*)(s + 8);
    }
#pragma unroll
    for (int j = 0; j < 2; j++)
#pragma unroll
        for (int p = 0; p < 2; p++)
            bPf[j][p] = *(const uint4*)(bsrc[j][p]);

    const int NK = DDIM / 32;
    for (int c = 0; c < NK; c++) {
#pragma unroll
        for (int p = 0; p < 2; p++) {
            *(uint4*)&sA[(p * 128 + ar) * ST + kh]     = aPf[p][0];
            *(uint4*)&sA[(p * 128 + ar) * ST + kh + 8] = aPf[p][1];
        }
#pragma unroll
        for (int j = 0; j < 2; j++)
#pragma unroll
            for (int p = 0; p < 2; p++)
                *(uint4*)&sB[((j * 2 + p) * 64 + br) * ST + bk] = bPf[j][p];
        __syncthreads();

        if (c + 1 < NK) {
            int k0 = (c + 1) * 32;
#pragma unroll
            for (int p = 0; p < 2; p++) {
                const __nv_bfloat16* s = (p ? axl : axh) + k0;
                aPf[p][0] = *(const uint4*)(s);
                aPf[p][1] = *(const uint4*)(s + 8);
            }
#pragma unroll
            for (int j = 0; j < 2; j++)
#pragma unroll
                for (int p = 0; p < 2; p++)
                    bPf[j][p] = *(const uint4*)(bsrc[j][p] + k0);
        }

#pragma unroll
        for (int kk = 0; kk < 2; kk++) {
            uint32_t aF[2][2][4];
#pragma unroll
            for (int p = 0; p < 2; p++)
#pragma unroll
                for (int mf = 0; mf < 2; mf++) {
                    uint32_t ad = sAu + 2u * (uint32_t)((p * 128 + wM * 32 + mf * 16 + arow_l) * ST + kk * 16 + acol_l);
                    LDSM4(aF[p][mf][0], aF[p][mf][1], aF[p][mf][2], aF[p][mf][3], ad);
                }
#pragma unroll
            for (int j = 0; j < 2; j++) {
                uint32_t bF[2][4][2];
#pragma unroll
                for (int p = 0; p < 2; p++)
#pragma unroll
                    for (int nfp = 0; nfp < 2; nfp++) {
                        uint32_t bd = sBu + 2u * (uint32_t)(((j * 2 + p) * 64 + wN * 32 + nfp * 16 + brow_l) * ST + kk * 16 + bcol_l);
                        LDSM4(bF[p][nfp * 2][0], bF[p][nfp * 2][1],
                              bF[p][nfp * 2 + 1][0], bF[p][nfp * 2 + 1][1], bd);
                    }
#pragma unroll
                for (int nf = 0; nf < 4; nf++)
#pragma unroll
                    for (int mf = 0; mf < 2; mf++) {
                        mma_acc(acc[j][mf][nf], aF[0][mf], bF[0][nf][0], bF[0][nf][1]);
                        mma_acc(acc[j][mf][nf], aF[0][mf], bF[1][nf][0], bF[1][nf][1]);
                        mma_acc(acc[j][mf][nf], aF[1][mf], bF[0][nf][0], bF[0][nf][1]);
                    }
            }
        }
        __syncthreads();
    }

    // epilogue -> bf16 hi/lo h planes
#pragma unroll
    for (int mf = 0; mf < 2; mf++)
#pragma unroll
        for (int nf = 0; nf < 4; nf++) {
            int col = n0 + wN * 32 + nf * 8 + tig * 2;
#pragma unroll
            for (int hh = 0; hh < 2; hh++) {
                int rl = row0 + wM * 32 + mf * 16 + g + hh * 8;
                if (rl < count) {
                    float wc = g_ew[e][rl];
                    float u0 = acc[0][mf][nf][hh * 2 + 0], s0 = acc[1][mf][nf][hh * 2 + 0];
                    float u1 = acc[0][mf][nf][hh * 2 + 1], s1 = acc[1][mf][nf][hh * 2 + 1];
                    float v0 = wc * u0 * coef * (s0 * (1.f / (1.f + __expf(-s0))));
                    float v1 = wc * u1 * coef * (s1 * (1.f / (1.f + __expf(-s1))));
                    uint32_t lo;
                    uint32_t hi = pack_hi(v0, v1, lo);
                    size_t idx = (size_t)(e * TTOK + rl) * HDIM + col;
                    *(uint32_t*)&g_hh[idx] = hi;
                    *(uint32_t*)&g_hl[idx] = lo;
                }
            }
        }
}

// ============================================================
// Generic upgate body (alpha not in {0,1}): R14-proven scalar path, 3 mats.
// smem: sA [2][128][36] (9216), sB [3][2][64][36] (13824); total 23040 shorts.
// ============================================================
#define GSA(p, r, k)    ((((p) * 128) + (r)) * 36 + (k))
#define GSB(j, p, r, k) ((((((j) * 2) + (p)) * 64) + (r)) * 36 + (k))
__device__ void upgate_gen(unsigned short* sbuf, const float* __restrict__ xg,
                           int e, int count, int row0, int n0, float al) {
    unsigned short* sA = sbuf;
    unsigned short* sB = sbuf + 9216;
    const __nv_bfloat16* wsl[3] = { g_wu, g_wg, g_wx };
    int tid = threadIdx.x, lane = tid & 31, w = tid >> 5;
    int wM = w & 3, wN = w >> 2;
    int g = lane >> 2, tig = lane & 3;
    int ar = tid >> 1, ahalf = (tid & 1) * 16;
    int tok = g_etok[e][row0 + ar];
    const float* asrc = xg + (size_t)tok * DDIM + ahalf;
    int br = tid >> 2, bk = (tid & 3) * 8;

    float4 aR[4];
    uint4  bR[3][2];
    float acc[3][2][4][4];
#pragma unroll
    for (int j = 0; j < 3; j++)
#pragma unroll
        for (int mf = 0; mf < 2; mf++)
#pragma unroll
            for (int nf = 0; nf < 4; nf++)
#pragma unroll
                for (int q = 0; q < 4; q++) acc[j][mf][nf][q] = 0.f;

#pragma unroll
    for (int q = 0; q < 4; q++) aR[q] = *(const float4*)(asrc + q * 4);
#pragma unroll
    for (int j = 0; j < 3; j++)
#pragma unroll
        for (int p = 0; p < 2; p++)
            bR[j][p] = *(const uint4*)(wsl[j] + ((size_t)(e * 2 + p) * HDIM + n0 + br) * DDIM + bk);

    const int NK = DDIM / 32;
    for (int c = 0; c < NK; c++) {
#pragma unroll
        for (int q = 0; q < 4; q++) {
            uint32_t l0, l1;
            uint32_t h0 = pack_hi(aR[q].x, aR[q].y, l0);
            uint32_t h1 = pack_hi(aR[q].z, aR[q].w, l1);
            int k = ahalf + q * 4;
            *(uint32_t*)&sA[GSA(0, ar, k)]     = h0;
            *(uint32_t*)&sA[GSA(0, ar, k + 2)] = h1;
            *(uint32_t*)&sA[GSA(1, ar, k)]     = l0;
            *(uint32_t*)&sA[GSA(1, ar, k + 2)] = l1;
        }
#pragma unroll
        for (int j = 0; j < 3; j++)
#pragma unroll
            for (int p = 0; p < 2; p++) {
                *(uint32_t*)&sB[GSB(j, p, br, bk)]     = bR[j][p].x;
                *(uint32_t*)&sB[GSB(j, p, br, bk + 2)] = bR[j][p].y;
                *(uint32_t*)&sB[GSB(j, p, br, bk + 4)] = bR[j][p].z;
                *(uint32_t*)&sB[GSB(j, p, br, bk + 6)] = bR[j][p].w;
            }
        __syncthreads();

        if (c + 1 < NK) {
            int k0 = (c + 1) * 32;
#pragma unroll
            for (int q = 0; q < 4; q++) aR[q] = *(const float4*)(asrc + k0 + q * 4);
#pragma unroll
            for (int j = 0; j < 3; j++)
#pragma unroll
                for (int p = 0; p < 2; p++)
                    bR[j][p] = *(const uint4*)(wsl[j] + ((size_t)(e * 2 + p) * HDIM + n0 + br) * DDIM + k0 + bk);
        }

#pragma unroll
        for (int kk = 0; kk < 2; kk++) {
            int kc = kk * 16 + tig * 2;
            uint32_t ah[2][4], alo_[2][4];
#pragma unroll
            for (int mf = 0; mf < 2; mf++) {
                int rb = wM * 32 + mf * 16;
                ah[mf][0]   = *(const uint32_t*)&sA[GSA(0, rb + g,     kc)];
                ah[mf][1]   = *(const uint32_t*)&sA[GSA(0, rb + g + 8, kc)];
                ah[mf][2]   = *(const uint32_t*)&sA[GSA(0, rb + g,     kc + 8)];
                ah[mf][3]   = *(const uint32_t*)&sA[GSA(0, rb + g + 8, kc + 8)];
                alo_[mf][0] = *(const uint32_t*)&sA[GSA(1, rb + g,     kc)];
                alo_[mf][1] = *(const uint32_t*)&sA[GSA(1, rb + g + 8, kc)];
                alo_[mf][2] = *(const uint32_t*)&sA[GSA(1, rb + g,     kc + 8)];
                alo_[mf][3] = *(const uint32_t*)&sA[GSA(1, rb + g + 8, kc + 8)];
            }
#pragma unroll
            for (int j = 0; j < 3; j++)
#pragma unroll
                for (int nf = 0; nf < 4; nf++) {
                    int brw = wN * 32 + nf * 8 + g;
                    uint32_t bh0 = *(const uint32_t*)&sB[GSB(j, 0, brw, kc)];
                    uint32_t bh1 = *(const uint32_t*)&sB[GSB(j, 0, brw, kc + 8)];
                    uint32_t bl0 = *(const uint32_t*)&sB[GSB(j, 1, brw, kc)];
                    uint32_t bl1 = *(const uint32_t*)&sB[GSB(j, 1, brw, kc + 8)];
#pragma unroll
                    for (int mf = 0; mf < 2; mf++) {
                        mma_acc(acc[j][mf][nf], ah[mf],   bh0, bh1);
                        mma_acc(acc[j][mf][nf], ah[mf],   bl0, bl1);
                        mma_acc(acc[j][mf][nf], alo_[mf], bh0, bh1);
                    }
                }
        }
        __syncthreads();
    }

#pragma unroll
    for (int mf = 0; mf < 2; mf++)
#pragma unroll
        for (int nf = 0; nf < 4; nf++) {
            int col = n0 + wN * 32 + nf * 8 + tig * 2;
#pragma unroll
            for (int hh = 0; hh < 2; hh++) {
                int rl = row0 + wM * 32 + mf * 16 + g + hh * 8;
                if (rl < count) {
                    float wc = g_ew[e][rl];
                    float v[2];
#pragma unroll
                    for (int q = 0; q < 2; q++) {
                        int i = hh * 2 + q;
                        float gv = acc[1][mf][nf][i];
                        float xv = acc[2][mf][nf][i];
                        float t = al * (gv * (1.f / (1.f + __expf(-gv))))
                                + (1.f - al) * (xv * (1.f / (1.f + __expf(-xv))));
                        v[q] = wc * acc[0][mf][nf][i] * t;
                    }
                    uint32_t lo;
                    uint32_t hi = pack_hi(v[0], v[1], lo);
                    size_t idx = (size_t)(e * TTOK + rl) * HDIM + col;
                    *(uint32_t*)&g_hh[idx] = hi;
                    *(uint32_t*)&g_hl[idx] = lo;
                }
            }
        }
}

__global__ void __launch_bounds__(256) k_upgate(const float* __restrict__ x,
                                                const float* __restrict__ alpha) {
    __shared__ __align__(16) unsigned short sbuf[23040];   // 45 KB
    int e = blockIdx.z;
    int count = g_ecount[e];
    int row0 = blockIdx.x * 128;
    if (row0 >= count) return;
    int n0 = blockIdx.y * 64;
    float al = alpha[e];
    bool hg = (al != 0.f), hx = (al != 1.f);
    if (hg && hx) {
        upgate_gen(sbuf, x, e, count, row0, n0, al);
    } else {
        const __nv_bfloat16* w2 = hg ? g_wg : g_wx;
        float coef = hg ? al : (1.f - al);
        upgate_fast(sbuf, e, count, row0, n0, w2, coef);
    }
}

// ============================================================
// K4: down-proj, ldmatrix + planes, atomicAdd scatter.
// smem: sA [2][128][40] (10240), sB [2][64][40] (5120) = 30 KB
// ============================================================
__global__ void __launch_bounds__(256) k_down(float* __restrict__ out) {
    __shared__ __align__(16) unsigned short sbuf[15360];
    const int ST = 40;
    unsigned short* sA = sbuf;
    unsigned short* sB = sbuf + 10240;
    int e = blockIdx.z;
    int count = g_ecount[e];
    int row0 = blockIdx.x * 128;
    if (row0 >= count) return;
    int n0 = blockIdx.y * 64;

    int tid = threadIdx.x, lane = tid & 31, w = tid >> 5;
    int wM = w & 3, wN = w >> 2;
    int g = lane >> 2, tig = lane & 3;
    int i8 = lane & 7, seg = lane >> 3;

    int ar = tid >> 1, kh = (tid & 1) * 16;
    const __nv_bfloat16* ahh = g_hh + (size_t)(e * TTOK + row0 + ar) * HDIM + kh;
    const __nv_bfloat16* ahl = g_hl + (size_t)(e * TTOK + row0 + ar) * HDIM + kh;
    int br = tid >> 2, bk = (tid & 3) * 8;
    const __nv_bfloat16* bsrc[2];
    bsrc[0] = g_wd + ((size_t)(e * 2 + 0) * DDIM + n0 + br) * HDIM + bk;
    bsrc[1] = g_wd + ((size_t)(e * 2 + 1) * DDIM + n0 + br) * HDIM + bk;

    uint32_t sAu = smem_u32(sA), sBu = smem_u32(sB);
    int arow_l = (seg & 1) * 8 + i8;
    int acol_l = (seg >> 1) * 8;
    int brow_l = (seg >> 1) * 8 + i8;
    int bcol_l = (seg & 1) * 8;

    float acc[2][4][4];
#pragma unroll
    for (int mf = 0; mf < 2; mf++)
#pragma unroll
        for (int nf = 0; nf < 4; nf++)
#pragma unroll
            for (int q = 0; q < 4; q++) acc[mf][nf][q] = 0.f;

    uint4 aPf[2][2], bPf[2];
#pragma unroll
    for (int p = 0; p < 2; p++) {
        const __nv_bfloat16* s = p ? ahl : ahh;
        aPf[p][0] = *(const uint4*)(s);
        aPf[p][1] = *(const uint4*)(s + 8);
    }
#pragma unroll
    for (int p = 0; p < 2; p++) bPf[p] = *(const uint4*)(bsrc[p]);

    const int NK = HDIM / 32;   // 44
    for (int c = 0; c < NK; c++) {
#pragma unroll
        for (int p = 0; p < 2; p++) {
            *(uint4*)&sA[(p * 128 + ar) * ST + kh]     = aPf[p][0];
            *(uint4*)&sA[(p * 128 + ar) * ST + kh + 8] = aPf[p][1];
        }
#pragma unroll
        for (int p = 0; p < 2; p++)
            *(uint4*)&sB[(p * 64 + br) * ST + bk] = bPf[p];
        __syncthreads();

        if (c + 1 < NK) {
            int k0 = (c + 1) * 32;
#pragma unroll
            for (int p = 0; p < 2; p++) {
                const __nv_bfloat16* s = (p ? ahl : ahh) + k0;
                aPf[p][0] = *(const uint4*)(s);
                aPf[p][1] = *(const uint4*)(s + 8);
            }
#pragma unroll
            for (int p = 0; p < 2; p++) bPf[p] = *(const uint4*)(bsrc[p] + k0);
        }

#pragma unroll
        for (int kk = 0; kk < 2; kk++) {
            uint32_t aF[2][2][4];
#pragma unroll
            for (int p = 0; p < 2; p++)
#pragma unroll
                for (int mf = 0; mf < 2; mf++) {
                    uint32_t ad = sAu + 2u * (uint32_t)((p * 128 + wM * 32 + mf * 16 + arow_l) * ST + kk * 16 + acol_l);
                    LDSM4(aF[p][mf][0], aF[p][mf][1], aF[p][mf][2], aF[p][mf][3], ad);
                }
            uint32_t bF[2][4][2];
#pragma unroll
            for (int p = 0; p < 2; p++)
#pragma unroll
                for (int nfp = 0; nfp < 2; nfp++) {
                    uint32_t bd = sBu + 2u * (uint32_t)((p * 64 + wN * 32 + nfp * 16 + brow_l) * ST + kk * 16 + bcol_l);
                    LDSM4(bF[p][nfp * 2][0], bF[p][nfp * 2][1],
                          bF[p][nfp * 2 + 1][0], bF[p][nfp * 2 + 1][1], bd);
                }
#pragma unroll
            for (int nf = 0; nf < 4; nf++)
#pragma unroll
                for (int mf = 0; mf < 2; mf++) {
                    mma_acc(acc[mf][nf], aF[0][mf], bF[0][nf][0], bF[0][nf][1]);
                    mma_acc(acc[mf][nf], aF[0][mf], bF[1][nf][0], bF[1][nf][1]);
                    mma_acc(acc[mf][nf], aF[1][mf], bF[0][nf][0], bF[0][nf][1]);
                }
        }
        __syncthreads();
    }

#pragma unroll
    for (int mf = 0; mf < 2; mf++)
#pragma unroll
        for (int nf = 0; nf < 4; nf++) {
            int col = n0 + wN * 32 + nf * 8 + tig * 2;
#pragma unroll
            for (int hh = 0; hh < 2; hh++) {
                int rl = row0 + wM * 32 + mf * 16 + g + hh * 8;
                if (rl < count) {
                    int tok = g_etok[e][rl];
                    float* orow = out + (size_t)tok * DDIM + col;
                    atomicAdd(&orow[0], acc[mf][nf][hh * 2 + 0]);
                    atomicAdd(&orow[1], acc[mf][nf][hh * 2 + 1]);
                }
            }
        }
}

// ===== K5: LB loss =====
__global__ void k_final(float* __restrict__ out, int out_size) {
    if (threadIdx.x == 0 && blockIdx.x == 0) {
        double s = 0.0;
        for (int e = 0; e < NE; e++) {
            double u = g_usage[e] / (double)TTOK - 1.0 / (double)NE;
            s += u * u;
        }
        float lb = (float)(0.01 * s / (double)NE);
        if (out_size > TTOK * DDIM) out[TTOK * DDIM] = lb;
    }
}

// ============================================================
extern "C" void kernel_launch(void* const* d_in, const int* in_sizes, int n_in,
                              void* d_out, int out_size) {
    const float* x     = (const float*)d_in[0];
    const float* Wr    = (const float*)d_in[1];
    const float* Wg    = (const float*)d_in[2];
    const float* Wu    = (const float*)d_in[3];
    const float* Wxp   = (const float*)d_in[4];
    const float* Wd    = (const float*)d_in[5];
    const float* alpha = (const float*)d_in[6];
    float* out = (float*)d_out;

    k_init<<<(TTOK * DDIM + 255) / 256, 256>>>(out);
    k_splitx<<<TTOK * DDIM / 4 / 256, 256>>>(x);

    dim3 tb(32, 8);
    dim3 tg_h(HDIM / 32, DDIM / 32, NE);
    k_tsplit<<<tg_h, tb>>>(Wg,  0, DDIM, HDIM);
    k_tsplit<<<tg_h, tb>>>(Wu,  1, DDIM, HDIM);
    k_tsplit<<<tg_h, tb>>>(Wxp, 2, DDIM, HDIM);
    dim3 tg_d(DDIM / 32, HDIM / 32, NE);
    k_tsplit<<<tg_d, tb>>>(Wd,  3, HDIM, DDIM);

    k_router<<<TTOK / 4, 128>>>(x, Wr);

    dim3 g2(TTOK / 128, HDIM / 64, NE);    // 64 x 22 x 8
    k_upgate<<<g2, 256>>>(x, alpha);

    dim3 g3(TTOK / 128, DDIM / 64, NE);    // 64 x 16 x 8
    k_down<<<g3, 256>>>(out);

    k_final<<<1, 32>>>(out, out_size);
}